// round 15
// baseline (speedup 1.0000x reference)
#include <cuda_runtime.h>
#include <cuda_fp16.h>
#include <math.h>
#include <stdint.h>

// Problem constants
#define BB 2
#define TT 1024
#define DD 1024
#define HH 16
#define LL 6
#define DHH 64
#define DFFF 2048
#define MROWS (BB*TT)   // 2048
#define D3 (3*DD)

// ---------------- scratch (device globals) ----------------------------------
__device__ float g_x[MROWS * DD];                              // residual
__device__ __half g_h_hi[MROWS*DD];                            // LN out
__device__ __half g_qkv_hi[MROWS*D3];                          // qkv (hi only)
__device__ __half g_o_hi[MROWS*DD];                            // attn out
__device__ __half g_a_hi[MROWS*DFFF];                          // gelu out
__device__ __half g_WqkvT[LL*D3*DD];
__device__ __half g_WoutT[LL*DD*DD];
__device__ __half g_W1T [LL*DFFF*DD];
__device__ __half g_W2T [LL*DD*DFFF];
__device__ int    g_ctr[32];                                   // tile counters

// ================= helpers =================
__device__ __forceinline__ uint32_t smem_u32(const void* p){
    uint32_t a;
    asm("{ .reg .u64 t; cvta.to.shared.u64 t, %1; cvt.u32.u64 %0, t; }"
        : "=r"(a) : "l"(p));
    return a;
}
__device__ __forceinline__ void ldsm_x4(uint32_t a, uint32_t& r0, uint32_t& r1,
                                        uint32_t& r2, uint32_t& r3){
    asm volatile("ldmatrix.sync.aligned.m8n8.x4.shared.b16 {%0,%1,%2,%3}, [%4];"
                 : "=r"(r0), "=r"(r1), "=r"(r2), "=r"(r3) : "r"(a));
}
__device__ __forceinline__ void ldsm_x2(uint32_t a, uint32_t& r0, uint32_t& r1){
    asm volatile("ldmatrix.sync.aligned.m8n8.x2.shared.b16 {%0,%1}, [%2];"
                 : "=r"(r0), "=r"(r1) : "r"(a));
}
__device__ __forceinline__ void ldsm_x2t(uint32_t a, uint32_t& r0, uint32_t& r1){
    asm volatile("ldmatrix.sync.aligned.m8n8.x2.trans.shared.b16 {%0,%1}, [%2];"
                 : "=r"(r0), "=r"(r1) : "r"(a));
}
__device__ __forceinline__ void mma_f16(float* c, const uint32_t* a,
                                        const uint32_t* b){
    asm volatile(
        "mma.sync.aligned.m16n8k16.row.col.f32.f16.f16.f32 "
        "{%0,%1,%2,%3}, {%4,%5,%6,%7}, {%8,%9}, {%0,%1,%2,%3};"
        : "+f"(c[0]), "+f"(c[1]), "+f"(c[2]), "+f"(c[3])
        : "r"(a[0]), "r"(a[1]), "r"(a[2]), "r"(a[3]), "r"(b[0]), "r"(b[1]));
}
__device__ __forceinline__ void cp16(uint32_t dst, const void* src){
    asm volatile("cp.async.cg.shared.global [%0], [%1], 16;"
                 :: "r"(dst), "l"(src));
}
#define CP_COMMIT() asm volatile("cp.async.commit_group;" ::: "memory")
#define CP_WAIT0()  asm volatile("cp.async.wait_group 0;" ::: "memory")

__device__ __forceinline__ uint32_t pack_h2(float lo_val, float hi_val){
    __half2 t = __floats2half2_rn(lo_val, hi_val);
    return *(uint32_t*)&t;
}

// ---------------- fused weight transpose + fp16 convert (ONE launch) --------
// per-layer tiles: qkv 24x32=768 | wout 8x32=256 | w1 16x32=512 | w2 8x64=512
__global__ void twk_all(const float* __restrict__ Wqkv,
                        const float* __restrict__ Wout,
                        const float* __restrict__ W1,
                        const float* __restrict__ W2,
                        __half* __restrict__ wqT, __half* __restrict__ woT,
                        __half* __restrict__ w1T, __half* __restrict__ w2T)
{
    __shared__ float t[32][129];
    int l = blockIdx.z;
    int tb = blockIdx.x;
    const float* W; __half* O; int K, N, bx, by;
    if (tb < 768)       { W = Wqkv; O = wqT; K = DD;   N = D3;
                          bx = tb % 24;          by = tb / 24; }
    else if (tb < 1024) { W = Wout; O = woT; K = DD;   N = DD;
                          bx = (tb - 768) % 8;   by = (tb - 768) / 8; }
    else if (tb < 1536) { W = W1;   O = w1T; K = DD;   N = DFFF;
                          bx = (tb - 1024) % 16; by = (tb - 1024) / 16; }
    else                { W = W2;   O = w2T; K = DFFF; N = DD;
                          bx = (tb - 1536) % 8;  by = (tb - 1536) / 8; }
    size_t loff = (size_t)l * K * N;
    const float* Wl = W + loff;
    __half* ol = O + loff;

    int n0 = bx * 128, k0 = by * 32;
    int tid = threadIdx.y * 32 + threadIdx.x;

    #pragma unroll
    for (int i = 0; i < 4; i++) {
        int idx = tid + (i << 8);
        int r = idx >> 5, c4 = idx & 31;
        float4 v = *(const float4*)(Wl + (size_t)(k0 + r) * N + n0 + c4 * 4);
        t[r][c4 * 4 + 0] = v.x;
        t[r][c4 * 4 + 1] = v.y;
        t[r][c4 * 4 + 2] = v.z;
        t[r][c4 * 4 + 3] = v.w;
    }
    __syncthreads();

    #pragma unroll
    for (int i = 0; i < 2; i++) {
        int idx = tid + (i << 8);
        int n = idx >> 2, kc = idx & 3;
        __half h[8];
        #pragma unroll
        for (int j = 0; j < 8; j++)
            h[j] = __float2half_rn(t[kc * 8 + j][n]);
        *(uint4*)(ol + (size_t)(n0 + n) * K + k0 + kc * 8) = *(uint4*)h;
    }
}

// ---------------- fused embedding + layer-0 LN1 (warp-per-row) --------------
__global__ __launch_bounds__(256) void embed_ln_kernel(
    const int* __restrict__ ids,
    const float* __restrict__ tok,
    const float* __restrict__ pos,
    const float* __restrict__ s,
    const float* __restrict__ b,
    float* __restrict__ x,
    __half* __restrict__ yhi)
{
    int lane = threadIdx.x & 31;
    int row  = (blockIdx.x << 3) + (threadIdx.x >> 5);
    int t    = row & (TT - 1);
    const float4* tok4 = (const float4*)(tok + (size_t)ids[row] * DD);
    const float4* pos4 = (const float4*)(pos + (size_t)t * DD);

    float4 v[8];
    float sum = 0.f, sq = 0.f;
    #pragma unroll
    for (int i = 0; i < 8; i++) {
        float4 a = tok4[i * 32 + lane];
        float4 p = pos4[i * 32 + lane];
        v[i] = make_float4(a.x + p.x, a.y + p.y, a.z + p.z, a.w + p.w);
        sum += v[i].x + v[i].y + v[i].z + v[i].w;
        sq  += v[i].x*v[i].x + v[i].y*v[i].y + v[i].z*v[i].z + v[i].w*v[i].w;
        ((float4*)(x + (size_t)row * DD))[i * 32 + lane] = v[i];
    }
    #pragma unroll
    for (int o = 16; o > 0; o >>= 1) {
        sum += __shfl_xor_sync(0xffffffffu, sum, o);
        sq  += __shfl_xor_sync(0xffffffffu, sq,  o);
    }
    float mean = sum * (1.f / DD);
    float inv  = rsqrtf(sq * (1.f / DD) - mean * mean + 1e-5f);

    #pragma unroll
    for (int i = 0; i < 8; i++) {
        int c4 = i * 32 + lane;
        float4 sv = ((const float4*)s)[c4];
        float4 bv = ((const float4*)b)[c4];
        float o0 = (v[i].x - mean) * inv * sv.x + bv.x;
        float o1 = (v[i].y - mean) * inv * sv.y + bv.y;
        float o2 = (v[i].z - mean) * inv * sv.z + bv.z;
        float o3 = (v[i].w - mean) * inv * sv.w + bv.w;
        size_t base = (size_t)row * DD + c4 * 4;
        *(uint32_t*)&yhi[base]     = pack_h2(o0, o1);
        *(uint32_t*)&yhi[base + 2] = pack_h2(o2, o3);
    }
}

// ---------------- layernorm: warp-per-row, no barriers ----------------------
// MODE: 0 = fp32 out, 2 = fp16 hi only
template<int MODE>
__global__ __launch_bounds__(256) void ln_kernel(
    const float* __restrict__ x,
    const float* __restrict__ s,
    const float* __restrict__ b,
    float* __restrict__ y,
    __half* __restrict__ yhi)
{
    int lane = threadIdx.x & 31;
    int row  = (blockIdx.x << 3) + (threadIdx.x >> 5);
    const float* xr = x + (size_t)row * DD;

    float4 v[8];
    float sum = 0.f, sq = 0.f;
    #pragma unroll
    for (int i = 0; i < 8; i++) {
        v[i] = ((const float4*)xr)[i * 32 + lane];
        sum += v[i].x + v[i].y + v[i].z + v[i].w;
        sq  += v[i].x*v[i].x + v[i].y*v[i].y + v[i].z*v[i].z + v[i].w*v[i].w;
    }
    #pragma unroll
    for (int o = 16; o > 0; o >>= 1) {
        sum += __shfl_xor_sync(0xffffffffu, sum, o);
        sq  += __shfl_xor_sync(0xffffffffu, sq,  o);
    }
    float mean = sum * (1.f / DD);
    float inv  = rsqrtf(sq * (1.f / DD) - mean * mean + 1e-5f);

    #pragma unroll
    for (int i = 0; i < 8; i++) {
        int c4 = i * 32 + lane;
        float4 sv = ((const float4*)s)[c4];
        float4 bv = ((const float4*)b)[c4];
        float o0 = (v[i].x - mean) * inv * sv.x + bv.x;
        float o1 = (v[i].y - mean) * inv * sv.y + bv.y;
        float o2 = (v[i].z - mean) * inv * sv.z + bv.z;
        float o3 = (v[i].w - mean) * inv * sv.w + bv.w;
        if (MODE == 0) {
            ((float4*)(y + (size_t)row * DD))[c4] = make_float4(o0, o1, o2, o3);
        } else {
            size_t base = (size_t)row * DD + c4 * 4;
            *(uint32_t*)&yhi[base]     = pack_h2(o0, o1);
            *(uint32_t*)&yhi[base + 2] = pack_h2(o2, o3);
        }
    }
}

// ================= persistent mma.sync fp16 GEMM =============================
// 1-term C = epi(A @ B^T). K-step 64, 2-stage, ONE barrier/stage, 2 CTAs/SM.
// Fixed grid 296; tiles claimed via atomic counter (work stealing).
// EPI: 1 = X+acc fp32, 2 = GELU -> fp16 hi, 4 = plain fp16 hi
#define GP 144
#define GTILE (128 * GP)              // 18432
#define GSTAGE (2 * GTILE)            // 36864 (A, B)
#define GSM_TOTAL (2 * GSTAGE)        // 73728 -> 2 CTAs/SM
#define GGRID 296

__device__ __forceinline__ void fill_cp(uint32_t dst, const __half* g,
                                        int K, int tid)
{
    #pragma unroll
    for (int i = 0; i < 4; i++) {
        int ch = tid + (i << 8);
        int r = ch >> 3, c = ch & 7;
        cp16(dst + r * GP + c * 16,
             (const char*)g + (size_t)r * K * 2 + c * 16);
    }
}

template<int EPI>
__global__ __launch_bounds__(256, 2) void gemm_mma(
    const __half* __restrict__ A,
    const __half* __restrict__ B,
    const float* __restrict__ X, float* __restrict__ C,
    __half* __restrict__ Chi,
    int M, int N, int K, int* __restrict__ ctr)
{
    extern __shared__ char sm[];
    __shared__ int s_tile;
    uint32_t sb = smem_u32(sm);
    int tid  = threadIdx.x;
    int lane = tid & 31, w = tid >> 5;
    int wm = (w >> 2) * 64, wn = (w & 3) * 32;
    int ntx = N >> 7, ntot = ntx * (M >> 7);
    int S = K >> 6;

    int aRow = wm + (lane & 15);
    int aSel = (lane >> 4);
    int bRow = wn + (lane & 7);
    int bSel = ((lane >> 3) & 1);

    for (;;) {
        if (tid == 0) s_tile = atomicAdd(ctr, 1);
        __syncthreads();
        int t = s_tile;
        if (t >= ntot) return;
        int m0 = (t / ntx) << 7, n0 = (t % ntx) << 7;

        const __half* pA = A + (size_t)m0 * K;
        const __half* pB = B + (size_t)n0 * K;
        float acc[4][4][4] = {};

        // prologue: stage 0 (writes buf0; last stage of previous tile was buf1)
        fill_cp(sb,         pA, K, tid);
        fill_cp(sb + GTILE, pB, K, tid);
        CP_COMMIT();

        for (int s = 0; s < S; s++) {
            CP_WAIT0();
            __syncthreads();

            if (s + 1 < S) {
                uint32_t nbuf = sb + ((s + 1) & 1) * GSTAGE;
                int k0 = (s + 1) << 6;
                fill_cp(nbuf,         pA + k0, K, tid);
                fill_cp(nbuf + GTILE, pB + k0, K, tid);
                CP_COMMIT();
            }

            uint32_t buf = sb + (s & 1) * GSTAGE;
            #pragma unroll
            for (int k16 = 0; k16 < 4; k16++) {
                uint32_t ah[4][4];
                #pragma unroll
                for (int mt = 0; mt < 4; mt++) {
                    uint32_t off = (uint32_t)(aRow + mt * 16) * GP +
                                   (uint32_t)(k16 * 2 + aSel) * 16;
                    ldsm_x4(buf + off, ah[mt][0], ah[mt][1], ah[mt][2], ah[mt][3]);
                }
                uint32_t bh[4][2];
                #pragma unroll
                for (int nt = 0; nt < 4; nt++) {
                    uint32_t off = (uint32_t)(bRow + nt * 8) * GP +
                                   (uint32_t)(k16 * 2 + bSel) * 16;
                    ldsm_x2(buf + GTILE + off, bh[nt][0], bh[nt][1]);
                }
                #pragma unroll
                for (int mt = 0; mt < 4; mt++)
                    #pragma unroll
                    for (int nt = 0; nt < 4; nt++)
                        mma_f16(acc[mt][nt], ah[mt], bh[nt]);
            }
        }

        #pragma unroll
        for (int mt = 0; mt < 4; mt++) {
            #pragma unroll
            for (int nt = 0; nt < 4; nt++) {
                float* cc = acc[mt][nt];
                int gr = m0 + wm + mt * 16 + (lane >> 2);
                int gc = n0 + wn + nt * 8 + (lane & 3) * 2;
                #pragma unroll
                for (int half = 0; half < 2; half++) {
                    size_t base = (size_t)(gr + half * 8) * N + gc;
                    float v0 = cc[half * 2], v1 = cc[half * 2 + 1];
                    if (EPI == 1) {
                        C[base]     = v0 + X[base];
                        C[base + 1] = v1 + X[base + 1];
                    } else if (EPI == 2) {
                        v0 = 0.5f * v0 * (1.f + erff(v0 * 0.70710678118654752f));
                        v1 = 0.5f * v1 * (1.f + erff(v1 * 0.70710678118654752f));
                        *(uint32_t*)&Chi[base] = pack_h2(v0, v1);
                    } else {
                        *(uint32_t*)&Chi[base] = pack_h2(v0, v1);
                    }
                }
            }
        }
    }
}

// ================= tensor-core flash attention ==============================
// QK^T 1-term, PV 1-term (all single fp16). Output hi only.
#define APITCH 144
#define ATILE (64 * APITCH)
#define ASTAGE (2 * ATILE)                  // Khi, Vhi
#define ATTN_SMEM (ATILE + 2 * ASTAGE)      // 46080

// fill K+V hi tiles for one jt: 1024 chunks, 128 threads -> 8 each
__device__ __forceinline__ void attn_fill2(uint32_t dstK, const __half* gk,
                                           const __half* gv, int tid)
{
    #pragma unroll
    for (int i = 0; i < 8; i++) {
        int ch = tid + (i << 7);
        int r = (ch & 511) >> 3, c = ch & 7;
        bool isK = ch < 512;
        const __half* src = isK ? gk : gv;
        uint32_t d = dstK + (isK ? 0 : ATILE) + r * APITCH + c * 16;
        cp16(d, (const char*)src + (size_t)r * D3 * 2 + c * 16);
    }
}

__global__ __launch_bounds__(128) void attn_mma(
    const __half* __restrict__ qkv_hi,
    __half* __restrict__ o_hi)
{
    extern __shared__ char sm[];
    uint32_t sb = smem_u32(sm);
    int p = blockIdx.x, bh = blockIdx.y;
    int b = bh >> 4, h = bh & 15;
    int tid = threadIdx.x, lane = tid & 31, w = tid >> 5;

    uint32_t sQ = sb;
    uint32_t sS0 = sb + ATILE;

    for (int sub = 0; sub < 2; sub++) {
        int qt = sub ? (15 - p) : p;

        size_t qrow = (size_t)(b * TT + qt * 64);
        const __half* gq = qkv_hi + qrow * D3 + h * DHH;

        // Q fill: 512 chunks / 128 thr = 4 each
        #pragma unroll
        for (int i = 0; i < 4; i++) {
            int ch = tid + (i << 7);
            int r = ch >> 3, c = ch & 7;
            cp16(sQ + r * APITCH + c * 16,
                 (const char*)gq + (size_t)r * D3 * 2 + c * 16);
        }
        {
            size_t krow = (size_t)(b * TT);
            attn_fill2(sS0, qkv_hi + krow * D3 + DD + h * DHH,
                            qkv_hi + krow * D3 + 2 * DD + h * DHH, tid);
        }
        CP_COMMIT();
        CP_WAIT0();
        __syncthreads();

        uint32_t qh[4][4];
        {
            uint32_t rowoff = (uint32_t)(w * 16 + (lane & 15)) * APITCH;
            uint32_t coloff = (uint32_t)(lane >> 4) * 16;
            #pragma unroll
            for (int kb = 0; kb < 4; kb++) {
                uint32_t off = rowoff + kb * 32 + coloff;
                ldsm_x4(sQ + off, qh[kb][0], qh[kb][1], qh[kb][2], qh[kb][3]);
            }
        }

        float oacc[8][4] = {};
        float mrow[2] = {-1e30f, -1e30f};
        float lrow[2] = {0.f, 0.f};

        int r0loc = w * 16 + (lane >> 2);
        int r0g = qt * 64 + r0loc;
        int cql = (lane & 3) * 2;

        for (int jt = 0; jt <= qt; jt++) {
            uint32_t buf = sS0 + (jt & 1) * ASTAGE;
            if (jt + 1 <= qt) {
                uint32_t nbuf = sS0 + ((jt + 1) & 1) * ASTAGE;
                size_t krow = (size_t)(b * TT + (jt + 1) * 64);
                attn_fill2(nbuf, qkv_hi + krow * D3 + DD + h * DHH,
                                 qkv_hi + krow * D3 + 2 * DD + h * DHH, tid);
                CP_COMMIT();
            }

            float s[8][4] = {};
            #pragma unroll
            for (int kb = 0; kb < 4; kb++) {
                uint32_t kcol = (uint32_t)(((lane >> 3) & 1) * 8 + kb * 16) * 2;
                #pragma unroll
                for (int nt = 0; nt < 8; nt++) {
                    uint32_t off = (uint32_t)(nt * 8 + (lane & 7)) * APITCH + kcol;
                    uint32_t kh0, kh1;
                    ldsm_x2(buf + off, kh0, kh1);
                    uint32_t bhK[2] = {kh0, kh1};
                    mma_f16(s[nt], qh[kb], bhK);
                }
            }

            bool diag = (jt == qt);
            #pragma unroll
            for (int nt = 0; nt < 8; nt++) {
                int colb = jt * 64 + nt * 8 + cql;
                #pragma unroll
                for (int q = 0; q < 4; q++) {
                    float v = s[nt][q] * 0.125f;
                    if (diag) {
                        int col = colb + (q & 1);
                        int row = r0g + (q >> 1) * 8;
                        if (col > row) v = -1e30f;
                    }
                    s[nt][q] = v;
                }
            }

            float mx0 = -1e30f, mx1 = -1e30f;
            #pragma unroll
            for (int nt = 0; nt < 8; nt++) {
                mx0 = fmaxf(mx0, fmaxf(s[nt][0], s[nt][1]));
                mx1 = fmaxf(mx1, fmaxf(s[nt][2], s[nt][3]));
            }
            mx0 = fmaxf(mx0, __shfl_xor_sync(0xffffffffu, mx0, 1));
            mx0 = fmaxf(mx0, __shfl_xor_sync(0xffffffffu, mx0, 2));
            mx1 = fmaxf(mx1, __shfl_xor_sync(0xffffffffu, mx1, 1));
            mx1 = fmaxf(mx1, __shfl_xor_sync(0xffffffffu, mx1, 2));
            float mn0 = fmaxf(mrow[0], mx0), mn1 = fmaxf(mrow[1], mx1);
            float sum0 = 0.f, sum1 = 0.f;
            #pragma unroll
            for (int nt = 0; nt < 8; nt++) {
                s[nt][0] = __expf(s[nt][0] - mn0);
                s[nt][1] = __expf(s[nt][1] - mn0);
                s[nt][2] = __expf(s[nt][2] - mn1);
                s[nt][3] = __expf(s[nt][3] - mn1);
                sum0 += s[nt][0] + s[nt][1];
                sum1 += s[nt][2] + s[nt][3];
            }
            sum0 += __shfl_xor_sync(0xffffffffu, sum0, 1);
            sum0 += __shfl_xor_sync(0xffffffffu, sum0, 2);
            sum1 += __shfl_xor_sync(0xffffffffu, sum1, 1);
            sum1 += __shfl_xor_sync(0xffffffffu, sum1, 2);
            float a0 = __expf(mrow[0] - mn0), a1 = __expf(mrow[1] - mn1);
            lrow[0] = lrow[0] * a0 + sum0;
            lrow[1] = lrow[1] * a1 + sum1;
            mrow[0] = mn0; mrow[1] = mn1;
            #pragma unroll
            for (int nt = 0; nt < 8; nt++) {
                oacc[nt][0] *= a0; oacc[nt][1] *= a0;
                oacc[nt][2] *= a1; oacc[nt][3] *= a1;
            }

            uint32_t vbase = buf + ATILE;
            #pragma unroll
            for (int kb = 0; kb < 4; kb++) {
                uint32_t ph[4];
                ph[0] = pack_h2(s[2*kb][0],   s[2*kb][1]);
                ph[1] = pack_h2(s[2*kb][2],   s[2*kb][3]);
                ph[2] = pack_h2(s[2*kb+1][0], s[2*kb+1][1]);
                ph[3] = pack_h2(s[2*kb+1][2], s[2*kb+1][3]);
                uint32_t vrow = (uint32_t)(kb * 16 + (lane & 15)) * APITCH;
                #pragma unroll
                for (int nt = 0; nt < 8; nt++) {
                    uint32_t vh0, vh1;
                    ldsm_x2t(vbase + vrow + nt * 16, vh0, vh1);
                    uint32_t bhV[2] = {vh0, vh1};
                    mma_f16(oacc[nt], ph, bhV);
                }
            }

            CP_WAIT0();
            __syncthreads();
        }

        float li0 = 1.f / lrow[0], li1 = 1.f / lrow[1];
        size_t orow0 = (size_t)(b * TT + r0g) * DD + h * DHH;
        #pragma unroll
        for (int nt = 0; nt < 8; nt++) {
            int gc = nt * 8 + cql;
            *(uint32_t*)&o_hi[orow0 + gc] =
                pack_h2(oacc[nt][0] * li0, oacc[nt][1] * li0);
            *(uint32_t*)&o_hi[orow0 + 8 * DD + gc] =
                pack_h2(oacc[nt][2] * li1, oacc[nt][3] * li1);
        }
    }
}

// ---------------- launcher ---------------------------------------------------
extern "C" void kernel_launch(void* const* d_in, const int* in_sizes, int n_in,
                              void* d_out, int out_size)
{
    const int*   ids  = (const int*)  d_in[0];
    const float* tok  = (const float*)d_in[1];
    const float* pos  = (const float*)d_in[2];
    const float* ln1s = (const float*)d_in[3];
    const float* ln1b = (const float*)d_in[4];
    const float* Wqkv = (const float*)d_in[5];
    const float* Wout = (const float*)d_in[6];
    const float* ln2s = (const float*)d_in[7];
    const float* ln2b = (const float*)d_in[8];
    const float* W1   = (const float*)d_in[9];
    const float* W2   = (const float*)d_in[10];
    const float* lnfs = (const float*)d_in[11];
    const float* lnfb = (const float*)d_in[12];
    float* out = (float*)d_out;

    float *x;
    __half *h_hi, *qkv_hi, *o_hi, *a_hi;
    __half *wqT, *woT, *w1T, *w2T;
    int* ctr;
    cudaGetSymbolAddress((void**)&x,      g_x);
    cudaGetSymbolAddress((void**)&h_hi,   g_h_hi);
    cudaGetSymbolAddress((void**)&qkv_hi, g_qkv_hi);
    cudaGetSymbolAddress((void**)&o_hi,   g_o_hi);
    cudaGetSymbolAddress((void**)&a_hi,   g_a_hi);
    cudaGetSymbolAddress((void**)&wqT,    g_WqkvT);
    cudaGetSymbolAddress((void**)&woT,    g_WoutT);
    cudaGetSymbolAddress((void**)&w1T,    g_W1T);
    cudaGetSymbolAddress((void**)&w2T,    g_W2T);
    cudaGetSymbolAddress((void**)&ctr,    g_ctr);

    cudaFuncSetAttribute(attn_mma,
                         cudaFuncAttributeMaxDynamicSharedMemorySize, ATTN_SMEM);
    cudaFuncSetAttribute(gemm_mma<1>,
                         cudaFuncAttributeMaxDynamicSharedMemorySize, GSM_TOTAL);
    cudaFuncSetAttribute(gemm_mma<2>,
                         cudaFuncAttributeMaxDynamicSharedMemorySize, GSM_TOTAL);
    cudaFuncSetAttribute(gemm_mma<4>,
                         cudaFuncAttributeMaxDynamicSharedMemorySize, GSM_TOTAL);

    // zero tile counters (captured as first graph node -> replay-safe)
    cudaMemsetAsync(ctr, 0, 32 * sizeof(int), 0);

    // fused weight transpose (1 launch)
    twk_all<<<dim3(2048, 1, LL), dim3(32, 8)>>>(Wqkv, Wout, W1, W2,
                                                wqT, woT, w1T, w2T);

    // fused embed + layer-0 LN1
    embed_ln_kernel<<<MROWS / 8, 256>>>(ids, tok, pos, ln1s, ln1b, x, h_hi);

    int ci = 0;
    for (int l = 0; l < LL; l++) {
        if (l > 0)
            ln_kernel<2><<<MROWS / 8, 256>>>(x, ln1s + (size_t)l * DD,
                                             ln1b + (size_t)l * DD,
                                             nullptr, h_hi);
        gemm_mma<4><<<GGRID, 256, GSM_TOTAL>>>(
            h_hi, wqT + (size_t)l * D3 * DD,
            nullptr, nullptr, qkv_hi, MROWS, D3, DD, ctr + ci++);
        attn_mma<<<dim3(TT / 128, BB * HH), 128, ATTN_SMEM>>>(qkv_hi, o_hi);
        gemm_mma<1><<<GGRID, 256, GSM_TOTAL>>>(
            o_hi, woT + (size_t)l * DD * DD,
            x, x, nullptr, MROWS, DD, DD, ctr + ci++);
        ln_kernel<2><<<MROWS / 8, 256>>>(x, ln2s + (size_t)l * DD,
                                         ln2b + (size_t)l * DD,
                                         nullptr, h_hi);
        gemm_mma<2><<<GGRID, 256, GSM_TOTAL>>>(
            h_hi, w1T + (size_t)l * DFFF * DD,
            nullptr, nullptr, a_hi, MROWS, DFFF, DD, ctr + ci++);
        gemm_mma<1><<<GGRID, 256, GSM_TOTAL>>>(
            a_hi, w2T + (size_t)l * DD * DFFF,
            x, x, nullptr, MROWS, DD, DFFF, ctr + ci++);
    }

    ln_kernel<0><<<MROWS / 8, 256>>>(x, lnfs, lnfb, out, nullptr);
}

// round 16
// speedup vs baseline: 1.2271x; 1.2271x over previous
#include <cuda_runtime.h>
#include <cuda_fp16.h>
#include <math.h>
#include <stdint.h>

// Problem constants
#define BB 2
#define TT 1024
#define DD 1024
#define HH 16
#define LL 6
#define DHH 64
#define DFFF 2048
#define MROWS (BB*TT)   // 2048
#define D3 (3*DD)

// ---------------- scratch (device globals) ----------------------------------
__device__ float g_x[MROWS * DD];                              // residual
__device__ __half g_h_hi[MROWS*DD];                            // LN out
__device__ __half g_qkv_hi[MROWS*D3];                          // qkv (hi only)
__device__ __half g_o_hi[MROWS*DD];                            // attn out
__device__ __half g_a_hi[MROWS*DFFF];                          // gelu out
__device__ __half g_WqkvT[LL*D3*DD];
__device__ __half g_WoutT[LL*DD*DD];
__device__ __half g_W1T [LL*DFFF*DD];
__device__ __half g_W2T [LL*DD*DFFF];

// ================= helpers =================
__device__ __forceinline__ uint32_t smem_u32(const void* p){
    uint32_t a;
    asm("{ .reg .u64 t; cvta.to.shared.u64 t, %1; cvt.u32.u64 %0, t; }"
        : "=r"(a) : "l"(p));
    return a;
}
__device__ __forceinline__ void ldsm_x4(uint32_t a, uint32_t& r0, uint32_t& r1,
                                        uint32_t& r2, uint32_t& r3){
    asm volatile("ldmatrix.sync.aligned.m8n8.x4.shared.b16 {%0,%1,%2,%3}, [%4];"
                 : "=r"(r0), "=r"(r1), "=r"(r2), "=r"(r3) : "r"(a));
}
__device__ __forceinline__ void ldsm_x2(uint32_t a, uint32_t& r0, uint32_t& r1){
    asm volatile("ldmatrix.sync.aligned.m8n8.x2.shared.b16 {%0,%1}, [%2];"
                 : "=r"(r0), "=r"(r1) : "r"(a));
}
__device__ __forceinline__ void ldsm_x2t(uint32_t a, uint32_t& r0, uint32_t& r1){
    asm volatile("ldmatrix.sync.aligned.m8n8.x2.trans.shared.b16 {%0,%1}, [%2];"
                 : "=r"(r0), "=r"(r1) : "r"(a));
}
__device__ __forceinline__ void mma_f16(float* c, const uint32_t* a,
                                        const uint32_t* b){
    asm volatile(
        "mma.sync.aligned.m16n8k16.row.col.f32.f16.f16.f32 "
        "{%0,%1,%2,%3}, {%4,%5,%6,%7}, {%8,%9}, {%0,%1,%2,%3};"
        : "+f"(c[0]), "+f"(c[1]), "+f"(c[2]), "+f"(c[3])
        : "r"(a[0]), "r"(a[1]), "r"(a[2]), "r"(a[3]), "r"(b[0]), "r"(b[1]));
}
__device__ __forceinline__ void cp16(uint32_t dst, const void* src){
    asm volatile("cp.async.cg.shared.global [%0], [%1], 16;"
                 :: "r"(dst), "l"(src));
}
#define CP_COMMIT() asm volatile("cp.async.commit_group;" ::: "memory")
#define CP_WAIT0()  asm volatile("cp.async.wait_group 0;" ::: "memory")

__device__ __forceinline__ uint32_t pack_h2(float lo_val, float hi_val){
    __half2 t = __floats2half2_rn(lo_val, hi_val);
    return *(uint32_t*)&t;
}

// ---------------- fused weight transpose + fp16 convert (ONE launch) --------
// per-layer tiles: qkv 24x32=768 | wout 8x32=256 | w1 16x32=512 | w2 8x64=512
__global__ void twk_all(const float* __restrict__ Wqkv,
                        const float* __restrict__ Wout,
                        const float* __restrict__ W1,
                        const float* __restrict__ W2,
                        __half* __restrict__ wqT, __half* __restrict__ woT,
                        __half* __restrict__ w1T, __half* __restrict__ w2T)
{
    __shared__ float t[32][129];
    int l = blockIdx.z;
    int tb = blockIdx.x;
    const float* W; __half* O; int K, N, bx, by;
    if (tb < 768)       { W = Wqkv; O = wqT; K = DD;   N = D3;
                          bx = tb % 24;          by = tb / 24; }
    else if (tb < 1024) { W = Wout; O = woT; K = DD;   N = DD;
                          bx = (tb - 768) % 8;   by = (tb - 768) / 8; }
    else if (tb < 1536) { W = W1;   O = w1T; K = DD;   N = DFFF;
                          bx = (tb - 1024) % 16; by = (tb - 1024) / 16; }
    else                { W = W2;   O = w2T; K = DFFF; N = DD;
                          bx = (tb - 1536) % 8;  by = (tb - 1536) / 8; }
    size_t loff = (size_t)l * K * N;
    const float* Wl = W + loff;
    __half* ol = O + loff;

    int n0 = bx * 128, k0 = by * 32;
    int tid = threadIdx.y * 32 + threadIdx.x;

    #pragma unroll
    for (int i = 0; i < 4; i++) {
        int idx = tid + (i << 8);
        int r = idx >> 5, c4 = idx & 31;
        float4 v = *(const float4*)(Wl + (size_t)(k0 + r) * N + n0 + c4 * 4);
        t[r][c4 * 4 + 0] = v.x;
        t[r][c4 * 4 + 1] = v.y;
        t[r][c4 * 4 + 2] = v.z;
        t[r][c4 * 4 + 3] = v.w;
    }
    __syncthreads();

    #pragma unroll
    for (int i = 0; i < 2; i++) {
        int idx = tid + (i << 8);
        int n = idx >> 2, kc = idx & 3;
        __half h[8];
        #pragma unroll
        for (int j = 0; j < 8; j++)
            h[j] = __float2half_rn(t[kc * 8 + j][n]);
        *(uint4*)(ol + (size_t)(n0 + n) * K + k0 + kc * 8) = *(uint4*)h;
    }
}

// ---------------- fused embedding + layer-0 LN1 (warp-per-row) --------------
__global__ __launch_bounds__(256) void embed_ln_kernel(
    const int* __restrict__ ids,
    const float* __restrict__ tok,
    const float* __restrict__ pos,
    const float* __restrict__ s,
    const float* __restrict__ b,
    float* __restrict__ x,
    __half* __restrict__ yhi)
{
    int lane = threadIdx.x & 31;
    int row  = (blockIdx.x << 3) + (threadIdx.x >> 5);
    int t    = row & (TT - 1);
    const float4* tok4 = (const float4*)(tok + (size_t)ids[row] * DD);
    const float4* pos4 = (const float4*)(pos + (size_t)t * DD);

    float4 v[8];
    float sum = 0.f, sq = 0.f;
    #pragma unroll
    for (int i = 0; i < 8; i++) {
        float4 a = tok4[i * 32 + lane];
        float4 p = pos4[i * 32 + lane];
        v[i] = make_float4(a.x + p.x, a.y + p.y, a.z + p.z, a.w + p.w);
        sum += v[i].x + v[i].y + v[i].z + v[i].w;
        sq  += v[i].x*v[i].x + v[i].y*v[i].y + v[i].z*v[i].z + v[i].w*v[i].w;
        ((float4*)(x + (size_t)row * DD))[i * 32 + lane] = v[i];
    }
    #pragma unroll
    for (int o = 16; o > 0; o >>= 1) {
        sum += __shfl_xor_sync(0xffffffffu, sum, o);
        sq  += __shfl_xor_sync(0xffffffffu, sq,  o);
    }
    float mean = sum * (1.f / DD);
    float inv  = rsqrtf(sq * (1.f / DD) - mean * mean + 1e-5f);

    #pragma unroll
    for (int i = 0; i < 8; i++) {
        int c4 = i * 32 + lane;
        float4 sv = ((const float4*)s)[c4];
        float4 bv = ((const float4*)b)[c4];
        float o0 = (v[i].x - mean) * inv * sv.x + bv.x;
        float o1 = (v[i].y - mean) * inv * sv.y + bv.y;
        float o2 = (v[i].z - mean) * inv * sv.z + bv.z;
        float o3 = (v[i].w - mean) * inv * sv.w + bv.w;
        size_t base = (size_t)row * DD + c4 * 4;
        *(uint32_t*)&yhi[base]     = pack_h2(o0, o1);
        *(uint32_t*)&yhi[base + 2] = pack_h2(o2, o3);
    }
}

// ---------------- layernorm: warp-per-row, no barriers ----------------------
// MODE: 0 = fp32 out, 2 = fp16 hi only
template<int MODE>
__global__ __launch_bounds__(256) void ln_kernel(
    const float* __restrict__ x,
    const float* __restrict__ s,
    const float* __restrict__ b,
    float* __restrict__ y,
    __half* __restrict__ yhi)
{
    int lane = threadIdx.x & 31;
    int row  = (blockIdx.x << 3) + (threadIdx.x >> 5);
    const float* xr = x + (size_t)row * DD;

    float4 v[8];
    float sum = 0.f, sq = 0.f;
    #pragma unroll
    for (int i = 0; i < 8; i++) {
        v[i] = ((const float4*)xr)[i * 32 + lane];
        sum += v[i].x + v[i].y + v[i].z + v[i].w;
        sq  += v[i].x*v[i].x + v[i].y*v[i].y + v[i].z*v[i].z + v[i].w*v[i].w;
    }
    #pragma unroll
    for (int o = 16; o > 0; o >>= 1) {
        sum += __shfl_xor_sync(0xffffffffu, sum, o);
        sq  += __shfl_xor_sync(0xffffffffu, sq,  o);
    }
    float mean = sum * (1.f / DD);
    float inv  = rsqrtf(sq * (1.f / DD) - mean * mean + 1e-5f);

    #pragma unroll
    for (int i = 0; i < 8; i++) {
        int c4 = i * 32 + lane;
        float4 sv = ((const float4*)s)[c4];
        float4 bv = ((const float4*)b)[c4];
        float o0 = (v[i].x - mean) * inv * sv.x + bv.x;
        float o1 = (v[i].y - mean) * inv * sv.y + bv.y;
        float o2 = (v[i].z - mean) * inv * sv.z + bv.z;
        float o3 = (v[i].w - mean) * inv * sv.w + bv.w;
        if (MODE == 0) {
            ((float4*)(y + (size_t)row * DD))[c4] = make_float4(o0, o1, o2, o3);
        } else {
            size_t base = (size_t)row * DD + c4 * 4;
            *(uint32_t*)&yhi[base]     = pack_h2(o0, o1);
            *(uint32_t*)&yhi[base + 2] = pack_h2(o2, o3);
        }
    }
}

// ================= mma.sync fp16 GEMM (256 threads, 8 warps) =================
// 1-term C = epi(A @ B^T). K-step 64, 2-stage, ONE barrier/stage, 2 CTAs/SM.
// EPI: 1 = X+acc fp32, 2 = GELU -> fp16 hi, 4 = plain fp16 hi
#define GP 144
#define GTILE (128 * GP)              // 18432
#define GSTAGE (2 * GTILE)            // 36864 (A, B)
#define GSM_TOTAL (2 * GSTAGE)        // 73728 -> 2 CTAs/SM

__device__ __forceinline__ void fill_cp(uint32_t dst, const __half* g,
                                        int K, int tid)
{
    #pragma unroll
    for (int i = 0; i < 4; i++) {
        int ch = tid + (i << 8);
        int r = ch >> 3, c = ch & 7;
        cp16(dst + r * GP + c * 16,
             (const char*)g + (size_t)r * K * 2 + c * 16);
    }
}

template<int EPI>
__global__ __launch_bounds__(256, 2) void gemm_mma(
    const __half* __restrict__ A,
    const __half* __restrict__ B,
    const float* __restrict__ X, float* __restrict__ C,
    __half* __restrict__ Chi,
    int M, int N, int K)
{
    extern __shared__ char sm[];
    uint32_t sb = smem_u32(sm);
    int tid  = threadIdx.x;
    int lane = tid & 31, w = tid >> 5;
    int wm = (w >> 2) * 64, wn = (w & 3) * 32;
    int m0 = blockIdx.y * 128, n0 = blockIdx.x * 128;

    const __half* pA = A + (size_t)m0 * K;
    const __half* pB = B + (size_t)n0 * K;

    float acc[4][4][4] = {};
    int S = K >> 6;

    fill_cp(sb,         pA, K, tid);
    fill_cp(sb + GTILE, pB, K, tid);
    CP_COMMIT();

    int aRow = wm + (lane & 15);
    int aSel = (lane >> 4);
    int bRow = wn + (lane & 7);
    int bSel = ((lane >> 3) & 1);

    for (int s = 0; s < S; s++) {
        CP_WAIT0();
        __syncthreads();

        if (s + 1 < S) {
            uint32_t nbuf = sb + ((s + 1) & 1) * GSTAGE;
            int k0 = (s + 1) << 6;
            fill_cp(nbuf,         pA + k0, K, tid);
            fill_cp(nbuf + GTILE, pB + k0, K, tid);
            CP_COMMIT();
        }

        uint32_t buf = sb + (s & 1) * GSTAGE;
        #pragma unroll
        for (int k16 = 0; k16 < 4; k16++) {
            uint32_t ah[4][4];
            #pragma unroll
            for (int mt = 0; mt < 4; mt++) {
                uint32_t off = (uint32_t)(aRow + mt * 16) * GP +
                               (uint32_t)(k16 * 2 + aSel) * 16;
                ldsm_x4(buf + off, ah[mt][0], ah[mt][1], ah[mt][2], ah[mt][3]);
            }
            uint32_t bh[4][2];
            #pragma unroll
            for (int nt = 0; nt < 4; nt++) {
                uint32_t off = (uint32_t)(bRow + nt * 8) * GP +
                               (uint32_t)(k16 * 2 + bSel) * 16;
                ldsm_x2(buf + GTILE + off, bh[nt][0], bh[nt][1]);
            }
            #pragma unroll
            for (int mt = 0; mt < 4; mt++)
                #pragma unroll
                for (int nt = 0; nt < 4; nt++)
                    mma_f16(acc[mt][nt], ah[mt], bh[nt]);
        }
    }

    #pragma unroll
    for (int mt = 0; mt < 4; mt++) {
        #pragma unroll
        for (int nt = 0; nt < 4; nt++) {
            float* cc = acc[mt][nt];
            int gr = m0 + wm + mt * 16 + (lane >> 2);
            int gc = n0 + wn + nt * 8 + (lane & 3) * 2;
            #pragma unroll
            for (int half = 0; half < 2; half++) {
                size_t base = (size_t)(gr + half * 8) * N + gc;
                float v0 = cc[half * 2], v1 = cc[half * 2 + 1];
                if (EPI == 1) {
                    C[base]     = v0 + X[base];
                    C[base + 1] = v1 + X[base + 1];
                } else if (EPI == 2) {
                    v0 = 0.5f * v0 * (1.f + erff(v0 * 0.70710678118654752f));
                    v1 = 0.5f * v1 * (1.f + erff(v1 * 0.70710678118654752f));
                    *(uint32_t*)&Chi[base] = pack_h2(v0, v1);
                } else {
                    *(uint32_t*)&Chi[base] = pack_h2(v0, v1);
                }
            }
        }
    }
}

// ================= tensor-core flash attention ==============================
// QK^T 1-term, PV 1-term (all single fp16). Output hi only.
#define APITCH 144
#define ATILE (64 * APITCH)
#define ASTAGE (2 * ATILE)                  // Khi, Vhi
#define ATTN_SMEM (ATILE + 2 * ASTAGE)      // 46080

// fill K+V hi tiles for one jt: 1024 chunks, 128 threads -> 8 each
__device__ __forceinline__ void attn_fill2(uint32_t dstK, const __half* gk,
                                           const __half* gv, int tid)
{
    #pragma unroll
    for (int i = 0; i < 8; i++) {
        int ch = tid + (i << 7);
        int r = (ch & 511) >> 3, c = ch & 7;
        bool isK = ch < 512;
        const __half* src = isK ? gk : gv;
        uint32_t d = dstK + (isK ? 0 : ATILE) + r * APITCH + c * 16;
        cp16(d, (const char*)src + (size_t)r * D3 * 2 + c * 16);
    }
}

__global__ __launch_bounds__(128) void attn_mma(
    const __half* __restrict__ qkv_hi,
    __half* __restrict__ o_hi)
{
    extern __shared__ char sm[];
    uint32_t sb = smem_u32(sm);
    int p = blockIdx.x, bh = blockIdx.y;
    int b = bh >> 4, h = bh & 15;
    int tid = threadIdx.x, lane = tid & 31, w = tid >> 5;

    uint32_t sQ = sb;
    uint32_t sS0 = sb + ATILE;

    for (int sub = 0; sub < 2; sub++) {
        int qt = sub ? (15 - p) : p;

        size_t qrow = (size_t)(b * TT + qt * 64);
        const __half* gq = qkv_hi + qrow * D3 + h * DHH;

        #pragma unroll
        for (int i = 0; i < 4; i++) {
            int ch = tid + (i << 7);
            int r = ch >> 3, c = ch & 7;
            cp16(sQ + r * APITCH + c * 16,
                 (const char*)gq + (size_t)r * D3 * 2 + c * 16);
        }
        {
            size_t krow = (size_t)(b * TT);
            attn_fill2(sS0, qkv_hi + krow * D3 + DD + h * DHH,
                            qkv_hi + krow * D3 + 2 * DD + h * DHH, tid);
        }
        CP_COMMIT();
        CP_WAIT0();
        __syncthreads();

        uint32_t qh[4][4];
        {
            uint32_t rowoff = (uint32_t)(w * 16 + (lane & 15)) * APITCH;
            uint32_t coloff = (uint32_t)(lane >> 4) * 16;
            #pragma unroll
            for (int kb = 0; kb < 4; kb++) {
                uint32_t off = rowoff + kb * 32 + coloff;
                ldsm_x4(sQ + off, qh[kb][0], qh[kb][1], qh[kb][2], qh[kb][3]);
            }
        }

        float oacc[8][4] = {};
        float mrow[2] = {-1e30f, -1e30f};
        float lrow[2] = {0.f, 0.f};

        int r0loc = w * 16 + (lane >> 2);
        int r0g = qt * 64 + r0loc;
        int cql = (lane & 3) * 2;

        for (int jt = 0; jt <= qt; jt++) {
            uint32_t buf = sS0 + (jt & 1) * ASTAGE;
            if (jt + 1 <= qt) {
                uint32_t nbuf = sS0 + ((jt + 1) & 1) * ASTAGE;
                size_t krow = (size_t)(b * TT + (jt + 1) * 64);
                attn_fill2(nbuf, qkv_hi + krow * D3 + DD + h * DHH,
                                 qkv_hi + krow * D3 + 2 * DD + h * DHH, tid);
                CP_COMMIT();
            }

            float s[8][4] = {};
            #pragma unroll
            for (int kb = 0; kb < 4; kb++) {
                uint32_t kcol = (uint32_t)(((lane >> 3) & 1) * 8 + kb * 16) * 2;
                #pragma unroll
                for (int nt = 0; nt < 8; nt++) {
                    uint32_t off = (uint32_t)(nt * 8 + (lane & 7)) * APITCH + kcol;
                    uint32_t kh0, kh1;
                    ldsm_x2(buf + off, kh0, kh1);
                    uint32_t bhK[2] = {kh0, kh1};
                    mma_f16(s[nt], qh[kb], bhK);
                }
            }

            bool diag = (jt == qt);
            #pragma unroll
            for (int nt = 0; nt < 8; nt++) {
                int colb = jt * 64 + nt * 8 + cql;
                #pragma unroll
                for (int q = 0; q < 4; q++) {
                    float v = s[nt][q] * 0.125f;
                    if (diag) {
                        int col = colb + (q & 1);
                        int row = r0g + (q >> 1) * 8;
                        if (col > row) v = -1e30f;
                    }
                    s[nt][q] = v;
                }
            }

            float mx0 = -1e30f, mx1 = -1e30f;
            #pragma unroll
            for (int nt = 0; nt < 8; nt++) {
                mx0 = fmaxf(mx0, fmaxf(s[nt][0], s[nt][1]));
                mx1 = fmaxf(mx1, fmaxf(s[nt][2], s[nt][3]));
            }
            mx0 = fmaxf(mx0, __shfl_xor_sync(0xffffffffu, mx0, 1));
            mx0 = fmaxf(mx0, __shfl_xor_sync(0xffffffffu, mx0, 2));
            mx1 = fmaxf(mx1, __shfl_xor_sync(0xffffffffu, mx1, 1));
            mx1 = fmaxf(mx1, __shfl_xor_sync(0xffffffffu, mx1, 2));
            float mn0 = fmaxf(mrow[0], mx0), mn1 = fmaxf(mrow[1], mx1);
            float sum0 = 0.f, sum1 = 0.f;
            #pragma unroll
            for (int nt = 0; nt < 8; nt++) {
                s[nt][0] = __expf(s[nt][0] - mn0);
                s[nt][1] = __expf(s[nt][1] - mn0);
                s[nt][2] = __expf(s[nt][2] - mn1);
                s[nt][3] = __expf(s[nt][3] - mn1);
                sum0 += s[nt][0] + s[nt][1];
                sum1 += s[nt][2] + s[nt][3];
            }
            sum0 += __shfl_xor_sync(0xffffffffu, sum0, 1);
            sum0 += __shfl_xor_sync(0xffffffffu, sum0, 2);
            sum1 += __shfl_xor_sync(0xffffffffu, sum1, 1);
            sum1 += __shfl_xor_sync(0xffffffffu, sum1, 2);
            float a0 = __expf(mrow[0] - mn0), a1 = __expf(mrow[1] - mn1);
            lrow[0] = lrow[0] * a0 + sum0;
            lrow[1] = lrow[1] * a1 + sum1;
            mrow[0] = mn0; mrow[1] = mn1;
            #pragma unroll
            for (int nt = 0; nt < 8; nt++) {
                oacc[nt][0] *= a0; oacc[nt][1] *= a0;
                oacc[nt][2] *= a1; oacc[nt][3] *= a1;
            }

            uint32_t vbase = buf + ATILE;
            #pragma unroll
            for (int kb = 0; kb < 4; kb++) {
                uint32_t ph[4];
                ph[0] = pack_h2(s[2*kb][0],   s[2*kb][1]);
                ph[1] = pack_h2(s[2*kb][2],   s[2*kb][3]);
                ph[2] = pack_h2(s[2*kb+1][0], s[2*kb+1][1]);
                ph[3] = pack_h2(s[2*kb+1][2], s[2*kb+1][3]);
                uint32_t vrow = (uint32_t)(kb * 16 + (lane & 15)) * APITCH;
                #pragma unroll
                for (int nt = 0; nt < 8; nt++) {
                    uint32_t vh0, vh1;
                    ldsm_x2t(vbase + vrow + nt * 16, vh0, vh1);
                    uint32_t bhV[2] = {vh0, vh1};
                    mma_f16(oacc[nt], ph, bhV);
                }
            }

            CP_WAIT0();
            __syncthreads();
        }

        float li0 = 1.f / lrow[0], li1 = 1.f / lrow[1];
        size_t orow0 = (size_t)(b * TT + r0g) * DD + h * DHH;
        #pragma unroll
        for (int nt = 0; nt < 8; nt++) {
            int gc = nt * 8 + cql;
            *(uint32_t*)&o_hi[orow0 + gc] =
                pack_h2(oacc[nt][0] * li0, oacc[nt][1] * li0);
            *(uint32_t*)&o_hi[orow0 + 8 * DD + gc] =
                pack_h2(oacc[nt][2] * li1, oacc[nt][3] * li1);
        }
    }
}

// ---------------- launcher ---------------------------------------------------
extern "C" void kernel_launch(void* const* d_in, const int* in_sizes, int n_in,
                              void* d_out, int out_size)
{
    const int*   ids  = (const int*)  d_in[0];
    const float* tok  = (const float*)d_in[1];
    const float* pos  = (const float*)d_in[2];
    const float* ln1s = (const float*)d_in[3];
    const float* ln1b = (const float*)d_in[4];
    const float* Wqkv = (const float*)d_in[5];
    const float* Wout = (const float*)d_in[6];
    const float* ln2s = (const float*)d_in[7];
    const float* ln2b = (const float*)d_in[8];
    const float* W1   = (const float*)d_in[9];
    const float* W2   = (const float*)d_in[10];
    const float* lnfs = (const float*)d_in[11];
    const float* lnfb = (const float*)d_in[12];
    float* out = (float*)d_out;

    float *x;
    __half *h_hi, *qkv_hi, *o_hi, *a_hi;
    __half *wqT, *woT, *w1T, *w2T;
    cudaGetSymbolAddress((void**)&x,      g_x);
    cudaGetSymbolAddress((void**)&h_hi,   g_h_hi);
    cudaGetSymbolAddress((void**)&qkv_hi, g_qkv_hi);
    cudaGetSymbolAddress((void**)&o_hi,   g_o_hi);
    cudaGetSymbolAddress((void**)&a_hi,   g_a_hi);
    cudaGetSymbolAddress((void**)&wqT,    g_WqkvT);
    cudaGetSymbolAddress((void**)&woT,    g_WoutT);
    cudaGetSymbolAddress((void**)&w1T,    g_W1T);
    cudaGetSymbolAddress((void**)&w2T,    g_W2T);

    cudaFuncSetAttribute(attn_mma,
                         cudaFuncAttributeMaxDynamicSharedMemorySize, ATTN_SMEM);
    cudaFuncSetAttribute(gemm_mma<1>,
                         cudaFuncAttributeMaxDynamicSharedMemorySize, GSM_TOTAL);
    cudaFuncSetAttribute(gemm_mma<2>,
                         cudaFuncAttributeMaxDynamicSharedMemorySize, GSM_TOTAL);
    cudaFuncSetAttribute(gemm_mma<4>,
                         cudaFuncAttributeMaxDynamicSharedMemorySize, GSM_TOTAL);

    // fused weight transpose (1 launch)
    twk_all<<<dim3(2048, 1, LL), dim3(32, 8)>>>(Wqkv, Wout, W1, W2,
                                                wqT, woT, w1T, w2T);

    // fused embed + layer-0 LN1
    embed_ln_kernel<<<MROWS / 8, 256>>>(ids, tok, pos, ln1s, ln1b, x, h_hi);

    for (int l = 0; l < LL; l++) {
        if (l > 0)
            ln_kernel<2><<<MROWS / 8, 256>>>(x, ln1s + (size_t)l * DD,
                                             ln1b + (size_t)l * DD,
                                             nullptr, h_hi);
        gemm_mma<4><<<dim3(D3 / 128, MROWS / 128), 256, GSM_TOTAL>>>(
            h_hi, wqT + (size_t)l * D3 * DD,
            nullptr, nullptr, qkv_hi, MROWS, D3, DD);
        attn_mma<<<dim3(TT / 128, BB * HH), 128, ATTN_SMEM>>>(qkv_hi, o_hi);
        gemm_mma<1><<<dim3(DD / 128, MROWS / 128), 256, GSM_TOTAL>>>(
            o_hi, woT + (size_t)l * DD * DD,
            x, x, nullptr, MROWS, DD, DD);
        ln_kernel<2><<<MROWS / 8, 256>>>(x, ln2s + (size_t)l * DD,
                                         ln2b + (size_t)l * DD,
                                         nullptr, h_hi);
        gemm_mma<2><<<dim3(DFFF / 128, MROWS / 128), 256, GSM_TOTAL>>>(
            h_hi, w1T + (size_t)l * DFFF * DD,
            nullptr, nullptr, a_hi, MROWS, DFFF, DD);
        gemm_mma<1><<<dim3(DD / 128, MROWS / 128), 256, GSM_TOTAL>>>(
            a_hi, w2T + (size_t)l * DD * DFFF,
            x, x, nullptr, MROWS, DD, DFFF);
    }

    ln_kernel<0><<<MROWS / 8, 256>>>(x, lnfs, lnfb, out, nullptr);
}